// round 1
// baseline (speedup 1.0000x reference)
#include <cuda_runtime.h>
#include <cuda_bf16.h>

// ---------------------------------------------------------------------------
// Model_63428077027896: channel-attention block, fp32 end-to-end.
// Stage 1: qkv  = Wqkv(12288x4096) @ x_b(4096x4096) + bqkv       (NN, bias M)
// Stage 2: q/k/v proj: per (b,h): A(512x4096) @ W^T(4096x4096)+b (NT, bias N)
// Stage 3: dot  = q2 @ k2^T * 0.125  (512x512, K=4096)           (NT)
// Stage 4: softmax rows of 512
// Stage 5: out  = attn(512x512) @ v2(512x4096)                   (NN)
// Stage 6: y    = Wout(4096x4096) @ out_b(4096x4096) + bout      (NN, bias M)
// All dims are multiples of the tile sizes -> no bounds checks.
// ---------------------------------------------------------------------------

#define BM 128
#define BN 128
#define BK 16
#define TM 8
#define TN 8
// 256 threads, 8x8 per thread, accumulators packed as f32x2.

// --- scratch (device globals; no dynamic allocation allowed) ---
__device__ float g_qkv [100663296]; // [2][12288][4096]
__device__ float g_proj[100663296]; // [3][2][8][512][4096]  q2,k2,v2
__device__ float g_dot [4194304];   // [2][8][512][512]
__device__ float g_out [33554432];  // [2][4096][4096]

__device__ __forceinline__ unsigned long long pack_dup(float a) {
    unsigned long long r;
    asm("mov.b64 %0, {%1, %1};" : "=l"(r) : "f"(a));
    return r;
}

union F2u { unsigned long long u; float f[2]; };

// BT = 1: B is [N,K] row-major (NT).  BT = 0: B is [K,N] row-major (NN).
template <int BT>
__global__ __launch_bounds__(256)
void gemm_kernel(const float* __restrict__ A, const float* __restrict__ B,
                 float* __restrict__ C,
                 int M, int N, int K,
                 long long sA1, long long sA2, int zshift, int zmask,
                 long long sB, long long sC,
                 const float* __restrict__ biasM,
                 const float* __restrict__ biasN,
                 float alpha)
{
    const int z = blockIdx.z;
    A += (long long)(z >> zshift) * sA1 + (long long)(z & zmask) * sA2;
    B += (long long)z * sB;
    C += (long long)z * sC;

    __shared__ __align__(16) float As[BK][BM + 4];
    __shared__ __align__(16) float Bs[BK][BN + 4];

    const int tid = threadIdx.x;
    const int m0 = blockIdx.y * BM;
    const int n0 = blockIdx.x * BN;
    const int tx = tid & 15;        // 0..15 -> N
    const int ty = tid >> 4;        // 0..15 -> M

    unsigned long long acc2[TM][TN / 2];
#pragma unroll
    for (int i = 0; i < TM; i++)
#pragma unroll
        for (int j = 0; j < TN / 2; j++) acc2[i][j] = 0ull;

    for (int k0 = 0; k0 < K; k0 += BK) {
        // ---- load A tile (always [M,K] row-major), store transposed ----
#pragma unroll
        for (int i = 0; i < 2; i++) {
            int slot = tid + i * 256;        // 0..511 float4 slots
            int m = slot >> 2;               // 0..127
            int kq = slot & 3;               // 0..3
            float4 v = *(const float4*)(A + (long long)(m0 + m) * K + k0 + kq * 4);
            As[kq * 4 + 0][m] = v.x;
            As[kq * 4 + 1][m] = v.y;
            As[kq * 4 + 2][m] = v.z;
            As[kq * 4 + 3][m] = v.w;
        }
        // ---- load B tile ----
        if (BT) {
#pragma unroll
            for (int i = 0; i < 2; i++) {
                int slot = tid + i * 256;
                int n = slot >> 2;
                int kq = slot & 3;
                float4 v = *(const float4*)(B + (long long)(n0 + n) * K + k0 + kq * 4);
                Bs[kq * 4 + 0][n] = v.x;
                Bs[kq * 4 + 1][n] = v.y;
                Bs[kq * 4 + 2][n] = v.z;
                Bs[kq * 4 + 3][n] = v.w;
            }
        } else {
#pragma unroll
            for (int i = 0; i < 2; i++) {
                int slot = tid + i * 256;
                int k = slot >> 5;           // 0..15
                int nq = slot & 31;          // 0..31
                float4 v = *(const float4*)(B + (long long)(k0 + k) * N + n0 + nq * 4);
                *(float4*)&Bs[k][nq * 4] = v;
            }
        }
        __syncthreads();

#pragma unroll
        for (int kk = 0; kk < BK; kk++) {
            float a[TM];
            *(float4*)&a[0] = *(const float4*)&As[kk][ty * TM];
            *(float4*)&a[4] = *(const float4*)&As[kk][ty * TM + 4];
            unsigned long long b2[TN / 2];
            *(ulonglong2*)&b2[0] = *(const ulonglong2*)&Bs[kk][tx * TN];
            *(ulonglong2*)&b2[2] = *(const ulonglong2*)&Bs[kk][tx * TN + 4];
#pragma unroll
            for (int i = 0; i < TM; i++) {
                unsigned long long a2 = pack_dup(a[i]);
#pragma unroll
                for (int j = 0; j < TN / 2; j++) {
                    asm("fma.rn.f32x2 %0, %1, %2, %0;"
                        : "+l"(acc2[i][j]) : "l"(a2), "l"(b2[j]));
                }
            }
        }
        __syncthreads();
    }

    // ---- epilogue ----
#pragma unroll
    for (int i = 0; i < TM; i++) {
        const int m = m0 + ty * TM + i;
        const float bm = biasM ? biasM[m] : 0.0f;
        float* crow = C + (long long)m * N + n0 + tx * TN;
#pragma unroll
        for (int j = 0; j < TN / 2; j++) {
            F2u u; u.u = acc2[i][j];
            int n = tx * TN + j * 2;
            float v0 = u.f[0] * alpha + bm;
            float v1 = u.f[1] * alpha + bm;
            if (biasN) {
                v0 += biasN[n0 + n];
                v1 += biasN[n0 + n + 1];
            }
            crow[j * 2]     = v0;
            crow[j * 2 + 1] = v1;
        }
    }
}

// softmax over rows of 512 (in place). grid = 8192 rows, block = 256.
__global__ void softmax_kernel(float* __restrict__ dot)
{
    const int row = blockIdx.x;
    float* p = dot + (long long)row * 512;
    __shared__ float red[256];
    const int t = threadIdx.x;

    float v0 = p[t], v1 = p[t + 256];
    float mx = fmaxf(v0, v1);
    red[t] = mx; __syncthreads();
#pragma unroll
    for (int s = 128; s > 0; s >>= 1) {
        if (t < s) red[t] = fmaxf(red[t], red[t + s]);
        __syncthreads();
    }
    mx = red[0]; __syncthreads();

    float e0 = expf(v0 - mx), e1 = expf(v1 - mx);
    red[t] = e0 + e1; __syncthreads();
#pragma unroll
    for (int s = 128; s > 0; s >>= 1) {
        if (t < s) red[t] += red[t + s];
        __syncthreads();
    }
    float inv = 1.0f / red[0];
    p[t] = e0 * inv;
    p[t + 256] = e1 * inv;
}

extern "C" void kernel_launch(void* const* d_in, const int* in_sizes, int n_in,
                              void* d_out, int out_size)
{
    const float* x    = (const float*)d_in[0];
    const float* Wqkv = (const float*)d_in[1];
    const float* bqkv = (const float*)d_in[2];
    const float* Wq   = (const float*)d_in[3];
    const float* bq   = (const float*)d_in[4];
    const float* Wk   = (const float*)d_in[5];
    const float* bk   = (const float*)d_in[6];
    const float* Wv   = (const float*)d_in[7];
    const float* bv   = (const float*)d_in[8];
    const float* Wout = (const float*)d_in[9];
    const float* bout = (const float*)d_in[10];
    float* y = (float*)d_out;

    float *qkv, *proj, *dot, *outb;
    cudaGetSymbolAddress((void**)&qkv,  g_qkv);
    cudaGetSymbolAddress((void**)&proj, g_proj);
    cudaGetSymbolAddress((void**)&dot,  g_dot);
    cudaGetSymbolAddress((void**)&outb, g_out);

    const long long S_X    = 16777216LL;  // 4096*4096
    const long long S_BQKV = 50331648LL;  // 12288*4096
    const long long S_H    = 2097152LL;   // 512*4096
    const long long S_DOT  = 262144LL;    // 512*512

    float* q2 = proj;
    float* k2 = proj + 33554432LL;
    float* v2 = proj + 67108864LL;

    // Stage 1: qkv[b] = Wqkv @ x[b] + bqkv   (M=12288, N=4096, K=4096, z=b)
    gemm_kernel<0><<<dim3(32, 96, 2), 256>>>(
        Wqkv, x, qkv, 12288, 4096, 4096,
        0, 0, 0, 0, S_X, S_BQKV, bqkv, nullptr, 1.0f);

    // Stage 2: per (b,h): proj of q, k, v.  z = b*8+h, A offset = b*S_BQKV + h*S_H
    gemm_kernel<1><<<dim3(32, 4, 16), 256>>>(
        qkv,              Wq, q2, 512, 4096, 4096,
        S_BQKV, S_H, 3, 7, 0, S_H, nullptr, bq, 1.0f);
    gemm_kernel<1><<<dim3(32, 4, 16), 256>>>(
        qkv + 16777216LL, Wk, k2, 512, 4096, 4096,
        S_BQKV, S_H, 3, 7, 0, S_H, nullptr, bk, 1.0f);
    gemm_kernel<1><<<dim3(32, 4, 16), 256>>>(
        qkv + 33554432LL, Wv, v2, 512, 4096, 4096,
        S_BQKV, S_H, 3, 7, 0, S_H, nullptr, bv, 1.0f);

    // Stage 3: dot = q2 @ k2^T * 0.125   (M=N=512, K=4096, z=(b,h))
    gemm_kernel<1><<<dim3(4, 4, 16), 256>>>(
        q2, k2, dot, 512, 512, 4096,
        S_H, 0, 0, 0, S_H, S_DOT, nullptr, nullptr, 0.125f);

    // Stage 4: softmax over 512-wide rows (2*8*512 rows)
    softmax_kernel<<<8192, 256>>>(dot);

    // Stage 5: out = attn @ v2   (M=512, N=4096, K=512, z=(b,h))
    gemm_kernel<0><<<dim3(32, 4, 16), 256>>>(
        dot, v2, outb, 512, 4096, 512,
        S_DOT, 0, 0, 0, S_H, S_H, nullptr, nullptr, 1.0f);

    // Stage 6: y[b] = Wout @ out[b] + bout   (M=N=K=4096, z=b)
    gemm_kernel<0><<<dim3(32, 32, 2), 256>>>(
        Wout, outb, y, 4096, 4096, 4096,
        0, 0, 0, 0, S_X, S_X, bout, nullptr, 1.0f);

    (void)in_sizes; (void)n_in; (void)out_size;
}